// round 12
// baseline (speedup 1.0000x reference)
#include <cuda_runtime.h>
#include <cuda_bf16.h>
#include <cstdint>

#define N_TOT 32768
#define K_TOT 8192
#define DDIM  64
#define ZQ_ELEMS 2097152
#define M_CTA 128
#define NB    64                  // codes per tile
#define NTILES (K_TOT / NB)       // 128
#define EPS_DOT 6e-5f
#define LIST_CAP (1u << 20)
#define CAND_CAP 2048

typedef unsigned long long ull;

// device scratch (no cudaMalloc allowed)
__device__ float g_enorm[K_TOT];
__device__ float g_znorm[N_TOT];
__device__ __align__(16) float g_zt[N_TOT * DDIM];             // 8MB z transposed
__device__ __align__(16) __nv_bfloat16 g_ebf16[K_TOT * DDIM];  // 1MB
__device__ unsigned g_list[LIST_CAP];                          // survivors (row<<13|k)
__device__ unsigned g_cnt;
__device__ ull   g_win[N_TOT];
__device__ float g_partial[128];

// ---------------- helpers ----------------
__device__ __forceinline__ uint32_t smem_u32(const void* p) {
    uint32_t a;
    asm("{ .reg .u64 t; cvta.to.shared.u64 t, %1; cvt.u32.u64 %0, t; }"
        : "=r"(a) : "l"(p));
    return a;
}
__device__ __forceinline__ unsigned packbf(float lo, float hi) {
    __nv_bfloat162 t = __floats2bfloat162_rn(lo, hi);
    return *reinterpret_cast<unsigned*>(&t);
}
__device__ __forceinline__ void mma16816(float c[4], const unsigned a[4],
                                         unsigned b0, unsigned b1) {
    asm volatile(
        "mma.sync.aligned.m16n8k16.row.col.f32.bf16.bf16.f32 "
        "{%0,%1,%2,%3}, {%4,%5,%6,%7}, {%8,%9}, {%0,%1,%2,%3};\n"
        : "+f"(c[0]), "+f"(c[1]), "+f"(c[2]), "+f"(c[3])
        : "r"(a[0]), "r"(a[1]), "r"(a[2]), "r"(a[3]), "r"(b0), "r"(b1));
}

// ---------------------------------------------------------------------------
// prep: ||e||^2 exact (reference order) + bf16 copy + zero survivor counter
// ---------------------------------------------------------------------------
__global__ void prep_kernel(const float* __restrict__ emb) {
    if (blockIdx.x == 0 && threadIdx.x == 0) g_cnt = 0;
    int k = blockIdx.x * blockDim.x + threadIdx.x;
    if (k < K_TOT) {
        const float* r = emb + (size_t)k * DDIM;
        __nv_bfloat16* o = g_ebf16 + (size_t)k * DDIM;
        float s = 0.f;
        #pragma unroll
        for (int c = 0; c < DDIM; ++c) {
            float v = r[c];
            s = __fadd_rn(s, __fmul_rn(v, v));
            o[c] = __float2bfloat16(v);
        }
        g_enorm[k] = s;
    }
}

// prep: ||z||^2 exact (sequential c=0..63) + transposed z copy + g_win init
__global__ __launch_bounds__(256) void znorm_kernel(const float* __restrict__ z) {
    __shared__ float zs[DDIM * 64];
    const int tid = threadIdx.x;
    const int n0  = blockIdx.x * 64;
    const int zbase = (n0 >> 12) * 262144 + (n0 & 4095);
    for (int r = tid; r < DDIM * 64; r += 256)
        zs[r] = z[zbase + (r >> 6) * 4096 + (r & 63)];
    __syncthreads();
    if (tid < 64) {
        float s = 0.f;
        #pragma unroll
        for (int c = 0; c < DDIM; ++c) {
            float v = zs[c * 64 + tid];
            s = __fadd_rn(s, __fmul_rn(v, v));
        }
        g_znorm[n0 + tid] = s;
        g_win[n0 + tid] = ~0ull;
    }
    #pragma unroll
    for (int i = 0; i < 16; ++i) {
        int f = tid + 256 * i;
        int r = f >> 6, d = f & 63;
        g_zt[(size_t)(n0 + r) * DDIM + d] = zs[d * 64 + r];
    }
}

// ---------------------------------------------------------------------------
// Pass A: bf16 mma GEMM; 4 warps x 32 rows; ldmatrix.x4 B loads (shared by
// 2 row-blocks); running rowmax; candidate emission + final refilter.
// grid = 256 CTAs (128 rows) x 128 threads.
// dyn smem 32KB: [0,16K) B double buffer | [16K,24K) cand_tag | [24K,32K) val
// ---------------------------------------------------------------------------
__global__ __launch_bounds__(128) void passA_kernel() {
    extern __shared__ __align__(16) char smem[];
    uint4*    bufs     = (uint4*)smem;                  // 2 x 8KB
    unsigned* cand_tag = (unsigned*)(smem + 16384);     // 2048
    float*    cand_val = (float*)(smem + 24576);        // 2048
    __shared__ unsigned s_cnt;
    __shared__ float rowmaxs[M_CTA];

    const int tid  = threadIdx.x;
    const int lane = tid & 31;
    const int w    = tid >> 5;            // 0..3, warp owns rows [32w,32w+32)
    const int n0   = blockIdx.x * M_CTA;

    if (tid == 0) s_cnt = 0;

    // stage B tile 0 into buffer 0 (16B-unit XOR swizzle inside code rows)
    {
        const uint4* src = (const uint4*)g_ebf16;
        #pragma unroll
        for (int i = 0; i < 4; ++i) {
            int q = tid + 128 * i;
            int code = q >> 3, j = q & 7;
            bufs[code * 8 + (j ^ (code & 7))] = src[q];
        }
    }

    const int g  = lane >> 2;
    const int c2 = (lane & 3) * 2;

    // A fragments for 2 row-blocks, straight from g_zt (one-time)
    unsigned a[2][4][4];
    #pragma unroll
    for (int b = 0; b < 2; ++b) {
        const float* zr0 = g_zt + (size_t)(n0 + 32 * w + 16 * b + g) * DDIM;
        const float* zr1 = zr0 + 8 * DDIM;
        #pragma unroll
        for (int s = 0; s < 4; ++s) {
            int k0 = 16 * s + c2;
            float2 p00 = *(const float2*)(zr0 + k0);
            float2 p10 = *(const float2*)(zr1 + k0);
            float2 p01 = *(const float2*)(zr0 + k0 + 8);
            float2 p11 = *(const float2*)(zr1 + k0 + 8);
            a[b][s][0] = packbf(p00.x, p00.y);
            a[b][s][1] = packbf(p10.x, p10.y);
            a[b][s][2] = packbf(p01.x, p01.y);
            a[b][s][3] = packbf(p11.x, p11.y);
        }
    }
    __syncthreads();

    const uint32_t bbase = smem_u32(smem);
    const int bn = lane & 7;          // code row within nt block
    const int jg = lane >> 3;         // chunk group for ldmatrix.x4

    float m0run[2] = {-1e30f, -1e30f};
    float m1run[2] = {-1e30f, -1e30f};

    for (int t = 0; t < NTILES; ++t) {
        const uint32_t cur = bbase + (t & 1) * 8192;

        if (t + 1 < NTILES) {
            const uint4* src = (const uint4*)(g_ebf16 + (size_t)(t + 1) * NB * DDIM);
            uint4* dst = bufs + ((t + 1) & 1) * 512;
            #pragma unroll
            for (int i = 0; i < 4; ++i) {
                int q = tid + 128 * i;
                int code = q >> 3, j = q & 7;
                dst[code * 8 + (j ^ (code & 7))] = src[q];
            }
        }

        float cf[2][8][4];
        #pragma unroll
        for (int b = 0; b < 2; ++b)
            #pragma unroll
            for (int nt = 0; nt < 8; ++nt)
                cf[b][nt][0] = cf[b][nt][1] = cf[b][nt][2] = cf[b][nt][3] = 0.f;

        #pragma unroll
        for (int nt = 0; nt < 8; ++nt) {
            int code = nt * 8 + bn;
            uint32_t rowb = cur + code * 128;
            unsigned r0, r1, r2, r3, r4, r5, r6, r7;
            uint32_t ad0 = rowb + (jg ^ (code & 7)) * 16;
            asm volatile("ldmatrix.sync.aligned.m8n8.x4.shared.b16 {%0,%1,%2,%3}, [%4];"
                         : "=r"(r0), "=r"(r1), "=r"(r2), "=r"(r3) : "r"(ad0));
            uint32_t ad1 = rowb + ((jg + 4) ^ (code & 7)) * 16;
            asm volatile("ldmatrix.sync.aligned.m8n8.x4.shared.b16 {%0,%1,%2,%3}, [%4];"
                         : "=r"(r4), "=r"(r5), "=r"(r6), "=r"(r7) : "r"(ad1));
            #pragma unroll
            for (int b = 0; b < 2; ++b) {
                mma16816(cf[b][nt], a[b][0], r0, r1);
                mma16816(cf[b][nt], a[b][1], r2, r3);
                mma16816(cf[b][nt], a[b][2], r4, r5);
                mma16816(cf[b][nt], a[b][3], r6, r7);
            }
        }

        // epilogue per row-block: local maxima, quad-reduce, emit candidates
        #pragma unroll
        for (int b = 0; b < 2; ++b) {
            float l0 = fmaxf(cf[b][0][0], cf[b][0][1]);
            float l1 = fmaxf(cf[b][0][2], cf[b][0][3]);
            #pragma unroll
            for (int nt = 1; nt < 8; ++nt) {
                l0 = fmaxf(l0, fmaxf(cf[b][nt][0], cf[b][nt][1]));
                l1 = fmaxf(l1, fmaxf(cf[b][nt][2], cf[b][nt][3]));
            }
            float m0 = fmaxf(l0, __shfl_xor_sync(~0u, l0, 1));
            m0 = fmaxf(m0, __shfl_xor_sync(~0u, m0, 2));
            float m1 = fmaxf(l1, __shfl_xor_sync(~0u, l1, 1));
            m1 = fmaxf(m1, __shfl_xor_sync(~0u, m1, 2));
            m0run[b] = fmaxf(m0run[b], m0);
            m1run[b] = fmaxf(m1run[b], m1);

            const unsigned row0 = n0 + 32 * w + 16 * b + g;
            const float th0 = m0run[b] - EPS_DOT;
            const float th1 = m1run[b] - EPS_DOT;
            if (l0 >= th0) {
                #pragma unroll
                for (int nt = 0; nt < 8; ++nt)
                    #pragma unroll
                    for (int q = 0; q < 2; ++q)
                        if (cf[b][nt][q] >= th0) {
                            unsigned tag = (row0 << 13) | (t * 64 + nt * 8 + c2 + q);
                            unsigned p = atomicAdd(&s_cnt, 1u);
                            if (p < CAND_CAP) { cand_tag[p] = tag; cand_val[p] = cf[b][nt][q]; }
                            else { unsigned gp = atomicAdd(&g_cnt, 1u);
                                   if (gp < LIST_CAP) g_list[gp] = tag; }
                        }
            }
            if (l1 >= th1) {
                #pragma unroll
                for (int nt = 0; nt < 8; ++nt)
                    #pragma unroll
                    for (int q = 0; q < 2; ++q)
                        if (cf[b][nt][2 + q] >= th1) {
                            unsigned tag = ((row0 + 8) << 13) | (t * 64 + nt * 8 + c2 + q);
                            unsigned p = atomicAdd(&s_cnt, 1u);
                            if (p < CAND_CAP) { cand_tag[p] = tag; cand_val[p] = cf[b][nt][2 + q]; }
                            else { unsigned gp = atomicAdd(&g_cnt, 1u);
                                   if (gp < LIST_CAP) g_list[gp] = tag; }
                        }
            }
        }

        __syncthreads();
    }

    // final per-row maxima, refilter candidates, flush survivors
    if ((lane & 3) == 0) {
        #pragma unroll
        for (int b = 0; b < 2; ++b) {
            rowmaxs[32 * w + 16 * b + g]     = m0run[b];
            rowmaxs[32 * w + 16 * b + g + 8] = m1run[b];
        }
    }
    __syncthreads();

    {
        const unsigned nloc = min(s_cnt, (unsigned)CAND_CAP);
        for (unsigned i = tid; i < nloc; i += 128) {
            unsigned tag = cand_tag[i];
            int rloc = (int)(tag >> 13) - n0;
            if (cand_val[i] >= rowmaxs[rloc] - EPS_DOT) {
                unsigned p = atomicAdd(&g_cnt, 1u);
                if (p < LIST_CAP) g_list[p] = tag;
            }
        }
    }
}

// ---------------------------------------------------------------------------
// Pass B: one thread per survivor (row,k); bit-exact sequential fp32 chain;
// atomicMin winner key (min d, ties -> lowest k)
// ---------------------------------------------------------------------------
__global__ __launch_bounds__(256) void passB_kernel(const float* __restrict__ emb) {
    const unsigned cnt = min(g_cnt, (unsigned)LIST_CAP);
    const unsigned stride = gridDim.x * 256;
    for (unsigned i = blockIdx.x * 256 + threadIdx.x; i < cnt; i += stride) {
        const unsigned e = g_list[i];
        const int row = e >> 13;
        const int k   = e & 8191;
        const float zn = g_znorm[row];
        const float4* zr = (const float4*)(g_zt + (size_t)row * DDIM);
        const float4* er = (const float4*)(emb + (size_t)k * DDIM);
        float s = 0.f;
        #pragma unroll
        for (int d4 = 0; d4 < 16; ++d4) {
            float4 av = zr[d4];
            float4 bv = er[d4];
            s = __fmaf_rn(av.x, bv.x, s);
            s = __fmaf_rn(av.y, bv.y, s);
            s = __fmaf_rn(av.z, bv.z, s);
            s = __fmaf_rn(av.w, bv.w, s);
        }
        float d = __fsub_rn(__fadd_rn(zn, g_enorm[k]), __fmul_rn(2.f, s));
        ull key = ((ull)__float_as_uint(d) << 32) | (unsigned)k;
        atomicMin(&g_win[row], key);
    }
}

// ---------------------------------------------------------------------------
// gather: z_q = fl(z + fl(zq - z)) (exact reference ops), loss partials, idx
// ---------------------------------------------------------------------------
__global__ __launch_bounds__(256) void gather_kernel(
    const float* __restrict__ z, const float* __restrict__ emb,
    float* __restrict__ out, int out_size)
{
    const int n = blockIdx.x * 256 + threadIdx.x;
    const int idx = (int)(g_win[n] & 8191u);
    const int obase = (n >> 12) * 262144 + (n & 4095);

    const float4* er = (const float4*)(emb + (size_t)idx * DDIM);
    float acc = 0.f;
    #pragma unroll
    for (int i = 0; i < DDIM / 4; ++i) {
        float4 e4 = er[i];
        float ev[4] = {e4.x, e4.y, e4.z, e4.w};
        #pragma unroll
        for (int c = 0; c < 4; ++c) {
            int d = 4 * i + c;
            float zv = z[obase + d * 4096];
            float df = __fsub_rn(ev[c], zv);
            out[obase + d * 4096] = __fadd_rn(zv, df);
            acc = fmaf(df, df, acc);
        }
    }
    if (out_size >= ZQ_ELEMS + 1 + N_TOT)
        out[ZQ_ELEMS + 1 + n] = (float)idx;

    __shared__ float red[256];
    red[threadIdx.x] = acc;
    __syncthreads();
    #pragma unroll
    for (int s = 128; s > 0; s >>= 1) {
        if (threadIdx.x < s) red[threadIdx.x] += red[threadIdx.x + s];
        __syncthreads();
    }
    if (threadIdx.x == 0) g_partial[blockIdx.x] = red[0];
}

__global__ void loss_kernel(float* __restrict__ out, int out_size) {
    __shared__ float red[128];
    red[threadIdx.x] = g_partial[threadIdx.x];
    __syncthreads();
    #pragma unroll
    for (int s = 64; s > 0; s >>= 1) {
        if (threadIdx.x < s) red[threadIdx.x] += red[threadIdx.x + s];
        __syncthreads();
    }
    if (threadIdx.x == 0 && out_size >= ZQ_ELEMS + 1) {
        float m = red[0] / (float)ZQ_ELEMS;
        out[ZQ_ELEMS] = __fadd_rn(m, __fmul_rn(0.25f, m));
    }
}

// ---------------------------------------------------------------------------
extern "C" void kernel_launch(void* const* d_in, const int* in_sizes, int n_in,
                              void* d_out, int out_size) {
    const float* z   = (const float*)d_in[0];
    const float* emb = (const float*)d_in[1];
    float* out = (float*)d_out;

    const int SMEM_A = 32768;   // 16KB B bufs + 16KB candidates
    static int smem_set = 0;
    if (!smem_set) {
        cudaFuncSetAttribute(passA_kernel,
            cudaFuncAttributeMaxDynamicSharedMemorySize, SMEM_A);
        smem_set = 1;
    }

    prep_kernel<<<K_TOT / 256, 256>>>(emb);
    znorm_kernel<<<N_TOT / 64, 256>>>(z);
    passA_kernel<<<N_TOT / M_CTA, 128, SMEM_A>>>();
    passB_kernel<<<128, 256>>>(emb);
    gather_kernel<<<N_TOT / 256, 256>>>(z, emb, out, out_size);
    loss_kernel<<<1, 128>>>(out, out_size);
}

// round 13
// speedup vs baseline: 1.8706x; 1.8706x over previous
#include <cuda_runtime.h>
#include <cuda_bf16.h>
#include <cstdint>

#define N_TOT 32768
#define K_TOT 8192
#define DDIM  64
#define ZQ_ELEMS 2097152
#define M_CTA 128
#define NB    64                  // codes per tile
#define NTILES (K_TOT / NB)       // 128
#define EPS_DOT 6e-5f
#define LIST_CAP (1u << 20)
#define CAND_CAP 2048

typedef unsigned long long ull;

// device scratch (no cudaMalloc allowed)
__device__ float g_enorm[K_TOT];
__device__ float g_znorm[N_TOT];
__device__ __align__(16) float g_zt[N_TOT * DDIM];             // 8MB z transposed
__device__ __align__(16) __nv_bfloat16 g_ebf16[K_TOT * DDIM];  // 1MB
__device__ unsigned g_list[LIST_CAP];                          // survivors (row<<13|k)
__device__ unsigned g_cnt;
__device__ ull   g_win[N_TOT];
__device__ float g_partial[128];

// ---------------- helpers ----------------
__device__ __forceinline__ uint32_t smem_u32(const void* p) {
    uint32_t a;
    asm("{ .reg .u64 t; cvta.to.shared.u64 t, %1; cvt.u32.u64 %0, t; }"
        : "=r"(a) : "l"(p));
    return a;
}
__device__ __forceinline__ unsigned packbf(float lo, float hi) {
    __nv_bfloat162 t = __floats2bfloat162_rn(lo, hi);
    return *reinterpret_cast<unsigned*>(&t);
}
__device__ __forceinline__ void mma16816(float c[4], const unsigned a[4],
                                         unsigned b0, unsigned b1) {
    asm volatile(
        "mma.sync.aligned.m16n8k16.row.col.f32.bf16.bf16.f32 "
        "{%0,%1,%2,%3}, {%4,%5,%6,%7}, {%8,%9}, {%0,%1,%2,%3};\n"
        : "+f"(c[0]), "+f"(c[1]), "+f"(c[2]), "+f"(c[3])
        : "r"(a[0]), "r"(a[1]), "r"(a[2]), "r"(a[3]), "r"(b0), "r"(b1));
}
__device__ __forceinline__ void cp16(uint32_t saddr, const void* gaddr) {
    asm volatile("cp.async.ca.shared.global [%0], [%1], 16;\n"
                 :: "r"(saddr), "l"(gaddr));
}

// ---------------------------------------------------------------------------
// prep: ||e||^2 exact (reference order) + bf16 copy + zero survivor counter
// ---------------------------------------------------------------------------
__global__ void prep_kernel(const float* __restrict__ emb) {
    if (blockIdx.x == 0 && threadIdx.x == 0) g_cnt = 0;
    int k = blockIdx.x * blockDim.x + threadIdx.x;
    if (k < K_TOT) {
        const float* r = emb + (size_t)k * DDIM;
        __nv_bfloat16* o = g_ebf16 + (size_t)k * DDIM;
        float s = 0.f;
        #pragma unroll
        for (int c = 0; c < DDIM; ++c) {
            float v = r[c];
            s = __fadd_rn(s, __fmul_rn(v, v));
            o[c] = __float2bfloat16(v);
        }
        g_enorm[k] = s;
    }
}

// prep: ||z||^2 exact (sequential c=0..63) + transposed z copy + g_win init
__global__ __launch_bounds__(256) void znorm_kernel(const float* __restrict__ z) {
    __shared__ float zs[DDIM * 64];
    const int tid = threadIdx.x;
    const int n0  = blockIdx.x * 64;
    const int zbase = (n0 >> 12) * 262144 + (n0 & 4095);
    for (int r = tid; r < DDIM * 64; r += 256)
        zs[r] = z[zbase + (r >> 6) * 4096 + (r & 63)];
    __syncthreads();
    if (tid < 64) {
        float s = 0.f;
        #pragma unroll
        for (int c = 0; c < DDIM; ++c) {
            float v = zs[c * 64 + tid];
            s = __fadd_rn(s, __fmul_rn(v, v));
        }
        g_znorm[n0 + tid] = s;
        g_win[n0 + tid] = ~0ull;
    }
    #pragma unroll
    for (int i = 0; i < 16; ++i) {
        int f = tid + 256 * i;
        int r = f >> 6, d = f & 63;
        g_zt[(size_t)(n0 + r) * DDIM + d] = zs[d * 64 + r];
    }
}

// ---------------------------------------------------------------------------
// Pass A: bf16 mma GEMM (round-10 shape: 8 warps x 16 rows), ldmatrix.x4 B,
// cp.async staging, running rowmax, candidate emission + final refilter.
// grid = 256 CTAs (128 rows) x 256 threads.
// dyn smem 32KB: [0,16K) B double buffer | [16K,24K) cand_tag | [24K,32K) val
// ---------------------------------------------------------------------------
__global__ __launch_bounds__(256) void passA_kernel() {
    extern __shared__ __align__(16) char smem[];
    unsigned* cand_tag = (unsigned*)(smem + 16384);     // 2048
    float*    cand_val = (float*)(smem + 24576);        // 2048
    __shared__ unsigned s_cnt;
    __shared__ float rowmaxs[M_CTA];

    const int tid  = threadIdx.x;
    const int lane = tid & 31;
    const int w    = tid >> 5;
    const int n0   = blockIdx.x * M_CTA;
    const uint32_t bbase = smem_u32(smem);

    if (tid == 0) s_cnt = 0;

    // stage B tile 0 into buffer 0 via cp.async (16B XOR swizzle in code rows)
    {
        const char* src = (const char*)g_ebf16;
        #pragma unroll
        for (int i = 0; i < 2; ++i) {
            int q = tid + 256 * i;
            int code = q >> 3, j = q & 7;
            cp16(bbase + (code * 8 + (j ^ (code & 7))) * 16, src + q * 16);
        }
        asm volatile("cp.async.commit_group;\n");
    }

    const int g  = lane >> 2;
    const int c2 = (lane & 3) * 2;
    const int rl = 16 * w + g;

    // A fragments straight from g_zt (one-time; L2-resident)
    unsigned a[4][4];
    {
        const float* zr0 = g_zt + (size_t)(n0 + rl) * DDIM;
        const float* zr1 = zr0 + 8 * DDIM;
        #pragma unroll
        for (int s = 0; s < 4; ++s) {
            int k0 = 16 * s + c2;
            float2 p00 = *(const float2*)(zr0 + k0);
            float2 p10 = *(const float2*)(zr1 + k0);
            float2 p01 = *(const float2*)(zr0 + k0 + 8);
            float2 p11 = *(const float2*)(zr1 + k0 + 8);
            a[s][0] = packbf(p00.x, p00.y);
            a[s][1] = packbf(p10.x, p10.y);
            a[s][2] = packbf(p01.x, p01.y);
            a[s][3] = packbf(p11.x, p11.y);
        }
    }
    asm volatile("cp.async.wait_group 0;\n" ::: "memory");
    __syncthreads();

    const int bn = lane & 7;          // code row within nt block
    const int jg = lane >> 3;         // 16B-chunk group for ldmatrix.x4
    const unsigned row0 = n0 + rl;    // rows for cf[.][0..1]; +8 for [2..3]

    float m0run = -1e30f, m1run = -1e30f;

    for (int t = 0; t < NTILES; ++t) {
        const uint32_t cur = bbase + (t & 1) * 8192;

        if (t + 1 < NTILES) {
            const char* src = (const char*)(g_ebf16 + (size_t)(t + 1) * NB * DDIM);
            const uint32_t dst = bbase + ((t + 1) & 1) * 8192;
            #pragma unroll
            for (int i = 0; i < 2; ++i) {
                int q = tid + 256 * i;
                int code = q >> 3, j = q & 7;
                cp16(dst + (code * 8 + (j ^ (code & 7))) * 16, src + q * 16);
            }
        }
        asm volatile("cp.async.commit_group;\n");

        float cf[8][4];
        #pragma unroll
        for (int nt = 0; nt < 8; ++nt) {
            cf[nt][0] = cf[nt][1] = cf[nt][2] = cf[nt][3] = 0.f;
            int code = nt * 8 + bn;
            uint32_t rowb = cur + code * 128;
            unsigned r0, r1, r2, r3, r4, r5, r6, r7;
            uint32_t ad0 = rowb + (jg ^ (code & 7)) * 16;
            asm volatile("ldmatrix.sync.aligned.m8n8.x4.shared.b16 {%0,%1,%2,%3}, [%4];"
                         : "=r"(r0), "=r"(r1), "=r"(r2), "=r"(r3) : "r"(ad0));
            uint32_t ad1 = rowb + ((jg + 4) ^ (code & 7)) * 16;
            asm volatile("ldmatrix.sync.aligned.m8n8.x4.shared.b16 {%0,%1,%2,%3}, [%4];"
                         : "=r"(r4), "=r"(r5), "=r"(r6), "=r"(r7) : "r"(ad1));
            mma16816(cf[nt], a[0], r0, r1);
            mma16816(cf[nt], a[1], r2, r3);
            mma16816(cf[nt], a[2], r4, r5);
            mma16816(cf[nt], a[3], r6, r7);
        }

        // per-thread local maxima, then 4-lane-group row max
        float l0 = fmaxf(cf[0][0], cf[0][1]), l1 = fmaxf(cf[0][2], cf[0][3]);
        #pragma unroll
        for (int nt = 1; nt < 8; ++nt) {
            l0 = fmaxf(l0, fmaxf(cf[nt][0], cf[nt][1]));
            l1 = fmaxf(l1, fmaxf(cf[nt][2], cf[nt][3]));
        }
        float m0 = fmaxf(l0, __shfl_xor_sync(~0u, l0, 1));
        m0 = fmaxf(m0, __shfl_xor_sync(~0u, m0, 2));
        float m1 = fmaxf(l1, __shfl_xor_sync(~0u, l1, 1));
        m1 = fmaxf(m1, __shfl_xor_sync(~0u, m1, 2));
        m0run = fmaxf(m0run, m0);
        m1run = fmaxf(m1run, m1);

        // rare: emit candidates vs running rowmax (superset of final survivors)
        const float th0 = m0run - EPS_DOT;
        const float th1 = m1run - EPS_DOT;
        if (l0 >= th0) {
            #pragma unroll
            for (int nt = 0; nt < 8; ++nt)
                #pragma unroll
                for (int q = 0; q < 2; ++q)
                    if (cf[nt][q] >= th0) {
                        unsigned tag = (row0 << 13) | (t * 64 + nt * 8 + c2 + q);
                        unsigned p = atomicAdd(&s_cnt, 1u);
                        if (p < CAND_CAP) { cand_tag[p] = tag; cand_val[p] = cf[nt][q]; }
                        else { unsigned gp = atomicAdd(&g_cnt, 1u);
                               if (gp < LIST_CAP) g_list[gp] = tag; }
                    }
        }
        if (l1 >= th1) {
            #pragma unroll
            for (int nt = 0; nt < 8; ++nt)
                #pragma unroll
                for (int q = 0; q < 2; ++q)
                    if (cf[nt][2 + q] >= th1) {
                        unsigned tag = ((row0 + 8) << 13) | (t * 64 + nt * 8 + c2 + q);
                        unsigned p = atomicAdd(&s_cnt, 1u);
                        if (p < CAND_CAP) { cand_tag[p] = tag; cand_val[p] = cf[nt][2 + q]; }
                        else { unsigned gp = atomicAdd(&g_cnt, 1u);
                               if (gp < LIST_CAP) g_list[gp] = tag; }
                    }
        }

        asm volatile("cp.async.wait_group 0;\n" ::: "memory");
        __syncthreads();
    }

    // final per-row maxima, refilter candidates, flush survivors
    if ((lane & 3) == 0) {
        rowmaxs[rl] = m0run;
        rowmaxs[rl + 8] = m1run;
    }
    __syncthreads();

    {
        const unsigned nloc = min(s_cnt, (unsigned)CAND_CAP);
        for (unsigned i = tid; i < nloc; i += 256) {
            unsigned tag = cand_tag[i];
            int rloc = (int)(tag >> 13) - n0;
            if (cand_val[i] >= rowmaxs[rloc] - EPS_DOT) {
                unsigned p = atomicAdd(&g_cnt, 1u);
                if (p < LIST_CAP) g_list[p] = tag;
            }
        }
    }
}

// ---------------------------------------------------------------------------
// Pass B: one thread per survivor (row,k); bit-exact sequential fp32 chain;
// atomicMin winner key (min d, ties -> lowest k)
// ---------------------------------------------------------------------------
__global__ __launch_bounds__(256) void passB_kernel(const float* __restrict__ emb) {
    const unsigned cnt = min(g_cnt, (unsigned)LIST_CAP);
    const unsigned stride = gridDim.x * 256;
    for (unsigned i = blockIdx.x * 256 + threadIdx.x; i < cnt; i += stride) {
        const unsigned e = g_list[i];
        const int row = e >> 13;
        const int k   = e & 8191;
        const float zn = g_znorm[row];
        const float4* zr = (const float4*)(g_zt + (size_t)row * DDIM);
        const float4* er = (const float4*)(emb + (size_t)k * DDIM);
        float s = 0.f;
        #pragma unroll
        for (int d4 = 0; d4 < 16; ++d4) {
            float4 av = zr[d4];
            float4 bv = er[d4];
            s = __fmaf_rn(av.x, bv.x, s);
            s = __fmaf_rn(av.y, bv.y, s);
            s = __fmaf_rn(av.z, bv.z, s);
            s = __fmaf_rn(av.w, bv.w, s);
        }
        float d = __fsub_rn(__fadd_rn(zn, g_enorm[k]), __fmul_rn(2.f, s));
        ull key = ((ull)__float_as_uint(d) << 32) | (unsigned)k;
        atomicMin(&g_win[row], key);
    }
}

// ---------------------------------------------------------------------------
// gather: z_q = fl(z + fl(zq - z)) (exact reference ops), loss partials, idx
// ---------------------------------------------------------------------------
__global__ __launch_bounds__(256) void gather_kernel(
    const float* __restrict__ z, const float* __restrict__ emb,
    float* __restrict__ out, int out_size)
{
    const int n = blockIdx.x * 256 + threadIdx.x;
    const int idx = (int)(g_win[n] & 8191u);
    const int obase = (n >> 12) * 262144 + (n & 4095);

    const float4* er = (const float4*)(emb + (size_t)idx * DDIM);
    float acc = 0.f;
    #pragma unroll
    for (int i = 0; i < DDIM / 4; ++i) {
        float4 e4 = er[i];
        float ev[4] = {e4.x, e4.y, e4.z, e4.w};
        #pragma unroll
        for (int c = 0; c < 4; ++c) {
            int d = 4 * i + c;
            float zv = z[obase + d * 4096];
            float df = __fsub_rn(ev[c], zv);
            out[obase + d * 4096] = __fadd_rn(zv, df);
            acc = fmaf(df, df, acc);
        }
    }
    if (out_size >= ZQ_ELEMS + 1 + N_TOT)
        out[ZQ_ELEMS + 1 + n] = (float)idx;

    __shared__ float red[256];
    red[threadIdx.x] = acc;
    __syncthreads();
    #pragma unroll
    for (int s = 128; s > 0; s >>= 1) {
        if (threadIdx.x < s) red[threadIdx.x] += red[threadIdx.x + s];
        __syncthreads();
    }
    if (threadIdx.x == 0) g_partial[blockIdx.x] = red[0];
}

__global__ void loss_kernel(float* __restrict__ out, int out_size) {
    __shared__ float red[128];
    red[threadIdx.x] = g_partial[threadIdx.x];
    __syncthreads();
    #pragma unroll
    for (int s = 64; s > 0; s >>= 1) {
        if (threadIdx.x < s) red[threadIdx.x] += red[threadIdx.x + s];
        __syncthreads();
    }
    if (threadIdx.x == 0 && out_size >= ZQ_ELEMS + 1) {
        float m = red[0] / (float)ZQ_ELEMS;
        out[ZQ_ELEMS] = __fadd_rn(m, __fmul_rn(0.25f, m));
    }
}

// ---------------------------------------------------------------------------
extern "C" void kernel_launch(void* const* d_in, const int* in_sizes, int n_in,
                              void* d_out, int out_size) {
    const float* z   = (const float*)d_in[0];
    const float* emb = (const float*)d_in[1];
    float* out = (float*)d_out;

    const int SMEM_A = 32768;   // 16KB B bufs + 16KB candidates
    static int smem_set = 0;
    if (!smem_set) {
        cudaFuncSetAttribute(passA_kernel,
            cudaFuncAttributeMaxDynamicSharedMemorySize, SMEM_A);
        smem_set = 1;
    }

    prep_kernel<<<K_TOT / 256, 256>>>(emb);
    znorm_kernel<<<N_TOT / 64, 256>>>(z);
    passA_kernel<<<N_TOT / M_CTA, 256, SMEM_A>>>();
    passB_kernel<<<128, 256>>>(emb);
    gather_kernel<<<N_TOT / 256, 256>>>(z, emb, out, out_size);
    loss_kernel<<<1, 128>>>(out, out_size);
}

// round 14
// speedup vs baseline: 1.9644x; 1.0502x over previous
#include <cuda_runtime.h>
#include <cuda_bf16.h>
#include <cstdint>

#define N_TOT 32768
#define K_TOT 8192
#define DDIM  64
#define ZQ_ELEMS 2097152
#define M_CTA 128
#define NB    64                  // codes per tile
#define NTILES (K_TOT / NB)       // 128
#define EPS_DOT 6e-5f
#define LIST_CAP (1u << 20)
#define CAND_CAP 2048
#define ZS_STRIDE 129             // padded staging stride (conflict-free)

typedef unsigned long long ull;

// device scratch (no cudaMalloc allowed)
__device__ float g_enorm[K_TOT];
__device__ float g_znorm[N_TOT];
__device__ __align__(16) float g_zt[N_TOT * DDIM];             // 8MB z transposed
__device__ __align__(16) __nv_bfloat16 g_ebf16[K_TOT * DDIM];  // 1MB
__device__ unsigned g_list[LIST_CAP];                          // survivors (row<<13|k)
__device__ unsigned g_cnt;
__device__ ull   g_win[N_TOT];
__device__ float g_partial[128];

// ---------------- helpers ----------------
__device__ __forceinline__ uint32_t smem_u32(const void* p) {
    uint32_t a;
    asm("{ .reg .u64 t; cvta.to.shared.u64 t, %1; cvt.u32.u64 %0, t; }"
        : "=r"(a) : "l"(p));
    return a;
}
__device__ __forceinline__ unsigned packbf(float lo, float hi) {
    __nv_bfloat162 t = __floats2bfloat162_rn(lo, hi);
    return *reinterpret_cast<unsigned*>(&t);
}
__device__ __forceinline__ void mma16816(float c[4], const unsigned a[4],
                                         unsigned b0, unsigned b1) {
    asm volatile(
        "mma.sync.aligned.m16n8k16.row.col.f32.bf16.bf16.f32 "
        "{%0,%1,%2,%3}, {%4,%5,%6,%7}, {%8,%9}, {%0,%1,%2,%3};\n"
        : "+f"(c[0]), "+f"(c[1]), "+f"(c[2]), "+f"(c[3])
        : "r"(a[0]), "r"(a[1]), "r"(a[2]), "r"(a[3]), "r"(b0), "r"(b1));
}
__device__ __forceinline__ void cp16(uint32_t saddr, const void* gaddr) {
    asm volatile("cp.async.ca.shared.global [%0], [%1], 16;\n"
                 :: "r"(saddr), "l"(gaddr));
}

// ---------------------------------------------------------------------------
// prep: ||e||^2 exact (reference order) + bf16 copy + g_win/g_cnt init
// ---------------------------------------------------------------------------
__global__ void prep_kernel(const float* __restrict__ emb) {
    if (blockIdx.x == 0 && threadIdx.x == 0) g_cnt = 0;
    int k = blockIdx.x * blockDim.x + threadIdx.x;
    if (k < K_TOT) {
        const float* r = emb + (size_t)k * DDIM;
        __nv_bfloat16* o = g_ebf16 + (size_t)k * DDIM;
        float s = 0.f;
        #pragma unroll
        for (int c = 0; c < DDIM; ++c) {
            float v = r[c];
            s = __fadd_rn(s, __fmul_rn(v, v));
            o[c] = __float2bfloat16(v);
        }
        g_enorm[k] = s;
        #pragma unroll
        for (int j = 0; j < 4; ++j) g_win[k + j * K_TOT] = ~0ull;
    }
}

// ---------------------------------------------------------------------------
// Pass A (fused): z staging + znorm + g_zt + bf16 mma GEMM + rowmax +
// candidate emission + final refilter.
// grid = 256 CTAs (128 rows) x 256 threads (8 warps x 16 rows).
// dyn smem 49408B: [0,16K) B double buffer
//                  [16K, +33024) phase 1: padded z staging [64][129]
//                  (mainloop overlay) [16K,24K) cand_tag | [24K,32K) cand_val
// ---------------------------------------------------------------------------
__global__ __launch_bounds__(256) void passA_kernel(const float* __restrict__ z) {
    extern __shared__ __align__(16) char smem[];
    float*    zs       = (float*)(smem + 16384);        // [64][129] floats
    unsigned* cand_tag = (unsigned*)(smem + 16384);     // 2048 (overlay)
    float*    cand_val = (float*)(smem + 24576);        // 2048 (overlay)
    __shared__ unsigned s_cnt;
    __shared__ float rowmaxs[M_CTA];

    const int tid  = threadIdx.x;
    const int lane = tid & 31;
    const int w    = tid >> 5;
    const int n0   = blockIdx.x * M_CTA;
    const int zbase = (n0 >> 12) * 262144 + (n0 & 4095);
    const uint32_t bbase = smem_u32(smem);

    if (tid == 0) s_cnt = 0;

    // stage B tile 0 into buffer 0 via cp.async (16B XOR swizzle in code rows)
    {
        const char* src = (const char*)g_ebf16;
        #pragma unroll
        for (int i = 0; i < 2; ++i) {
            int q = tid + 256 * i;
            int code = q >> 3, j = q & 7;
            cp16(bbase + (code * 8 + (j ^ (code & 7))) * 16, src + q * 16);
        }
        asm volatile("cp.async.commit_group;\n");
    }

    // ---- phase 1: stage z [d][r] padded (coalesced gmem, clean smem) ----
    #pragma unroll
    for (int i = 0; i < 32; ++i) {
        int f = tid + 256 * i;
        int d = f >> 7, r = f & 127;
        zs[d * ZS_STRIDE + r] = z[zbase + d * 4096 + r];
    }
    __syncthreads();

    // znorm (bit-exact sequential c=0..63) for this CTA's 128 rows
    if (tid < 128) {
        float s = 0.f;
        #pragma unroll
        for (int c = 0; c < DDIM; ++c) {
            float v = zs[c * ZS_STRIDE + tid];
            s = __fadd_rn(s, __fmul_rn(v, v));
        }
        g_znorm[n0 + tid] = s;
    }
    // write g_zt rows (conflict-free smem reads, coalesced gmem writes)
    #pragma unroll
    for (int i = 0; i < 32; ++i) {
        int f = tid + 256 * i;
        int r = f >> 6, d = f & 63;
        g_zt[(size_t)(n0 + r) * DDIM + d] = zs[d * ZS_STRIDE + r];
    }

    const int g  = lane >> 2;
    const int c2 = (lane & 3) * 2;
    const int rl = 16 * w + g;

    // A fragments from padded staging
    unsigned a[4][4];
    #pragma unroll
    for (int s = 0; s < 4; ++s) {
        int k0 = 16 * s + c2;
        a[s][0] = packbf(zs[k0 * ZS_STRIDE + rl],           zs[(k0 + 1) * ZS_STRIDE + rl]);
        a[s][1] = packbf(zs[k0 * ZS_STRIDE + rl + 8],       zs[(k0 + 1) * ZS_STRIDE + rl + 8]);
        a[s][2] = packbf(zs[(k0 + 8) * ZS_STRIDE + rl],     zs[(k0 + 9) * ZS_STRIDE + rl]);
        a[s][3] = packbf(zs[(k0 + 8) * ZS_STRIDE + rl + 8], zs[(k0 + 9) * ZS_STRIDE + rl + 8]);
    }
    asm volatile("cp.async.wait_group 0;\n" ::: "memory");
    __syncthreads();   // zs region becomes candidate arrays

    const int bn = lane & 7;          // code row within nt block
    const int jg = lane >> 3;         // 16B-chunk group for ldmatrix.x4
    const unsigned row0 = n0 + rl;    // rows for cf[.][0..1]; +8 for [2..3]

    float m0run = -1e30f, m1run = -1e30f;

    for (int t = 0; t < NTILES; ++t) {
        const uint32_t cur = bbase + (t & 1) * 8192;

        if (t + 1 < NTILES) {
            const char* src = (const char*)(g_ebf16 + (size_t)(t + 1) * NB * DDIM);
            const uint32_t dst = bbase + ((t + 1) & 1) * 8192;
            #pragma unroll
            for (int i = 0; i < 2; ++i) {
                int q = tid + 256 * i;
                int code = q >> 3, j = q & 7;
                cp16(dst + (code * 8 + (j ^ (code & 7))) * 16, src + q * 16);
            }
        }
        asm volatile("cp.async.commit_group;\n");

        float cf[8][4];
        #pragma unroll
        for (int nt = 0; nt < 8; ++nt) {
            cf[nt][0] = cf[nt][1] = cf[nt][2] = cf[nt][3] = 0.f;
            int code = nt * 8 + bn;
            uint32_t rowb = cur + code * 128;
            unsigned r0, r1, r2, r3, r4, r5, r6, r7;
            uint32_t ad0 = rowb + (jg ^ (code & 7)) * 16;
            asm volatile("ldmatrix.sync.aligned.m8n8.x4.shared.b16 {%0,%1,%2,%3}, [%4];"
                         : "=r"(r0), "=r"(r1), "=r"(r2), "=r"(r3) : "r"(ad0));
            uint32_t ad1 = rowb + ((jg + 4) ^ (code & 7)) * 16;
            asm volatile("ldmatrix.sync.aligned.m8n8.x4.shared.b16 {%0,%1,%2,%3}, [%4];"
                         : "=r"(r4), "=r"(r5), "=r"(r6), "=r"(r7) : "r"(ad1));
            mma16816(cf[nt], a[0], r0, r1);
            mma16816(cf[nt], a[1], r2, r3);
            mma16816(cf[nt], a[2], r4, r5);
            mma16816(cf[nt], a[3], r6, r7);
        }

        // per-thread local maxima, then 4-lane-group row max
        float l0 = fmaxf(cf[0][0], cf[0][1]), l1 = fmaxf(cf[0][2], cf[0][3]);
        #pragma unroll
        for (int nt = 1; nt < 8; ++nt) {
            l0 = fmaxf(l0, fmaxf(cf[nt][0], cf[nt][1]));
            l1 = fmaxf(l1, fmaxf(cf[nt][2], cf[nt][3]));
        }
        float m0 = fmaxf(l0, __shfl_xor_sync(~0u, l0, 1));
        m0 = fmaxf(m0, __shfl_xor_sync(~0u, m0, 2));
        float m1 = fmaxf(l1, __shfl_xor_sync(~0u, l1, 1));
        m1 = fmaxf(m1, __shfl_xor_sync(~0u, m1, 2));
        m0run = fmaxf(m0run, m0);
        m1run = fmaxf(m1run, m1);

        // rare: emit candidates vs running rowmax (superset of final survivors)
        const float th0 = m0run - EPS_DOT;
        const float th1 = m1run - EPS_DOT;
        if (l0 >= th0) {
            #pragma unroll
            for (int nt = 0; nt < 8; ++nt)
                #pragma unroll
                for (int q = 0; q < 2; ++q)
                    if (cf[nt][q] >= th0) {
                        unsigned tag = (row0 << 13) | (t * 64 + nt * 8 + c2 + q);
                        unsigned p = atomicAdd(&s_cnt, 1u);
                        if (p < CAND_CAP) { cand_tag[p] = tag; cand_val[p] = cf[nt][q]; }
                        else { unsigned gp = atomicAdd(&g_cnt, 1u);
                               if (gp < LIST_CAP) g_list[gp] = tag; }
                    }
        }
        if (l1 >= th1) {
            #pragma unroll
            for (int nt = 0; nt < 8; ++nt)
                #pragma unroll
                for (int q = 0; q < 2; ++q)
                    if (cf[nt][2 + q] >= th1) {
                        unsigned tag = ((row0 + 8) << 13) | (t * 64 + nt * 8 + c2 + q);
                        unsigned p = atomicAdd(&s_cnt, 1u);
                        if (p < CAND_CAP) { cand_tag[p] = tag; cand_val[p] = cf[nt][2 + q]; }
                        else { unsigned gp = atomicAdd(&g_cnt, 1u);
                               if (gp < LIST_CAP) g_list[gp] = tag; }
                    }
        }

        asm volatile("cp.async.wait_group 0;\n" ::: "memory");
        __syncthreads();
    }

    // final per-row maxima, refilter candidates, flush survivors
    if ((lane & 3) == 0) {
        rowmaxs[rl] = m0run;
        rowmaxs[rl + 8] = m1run;
    }
    __syncthreads();

    {
        const unsigned nloc = min(s_cnt, (unsigned)CAND_CAP);
        for (unsigned i = tid; i < nloc; i += 256) {
            unsigned tag = cand_tag[i];
            int rloc = (int)(tag >> 13) - n0;
            if (cand_val[i] >= rowmaxs[rloc] - EPS_DOT) {
                unsigned p = atomicAdd(&g_cnt, 1u);
                if (p < LIST_CAP) g_list[p] = tag;
            }
        }
    }
}

// ---------------------------------------------------------------------------
// Pass B: one thread per survivor (row,k); bit-exact sequential fp32 chain;
// atomicMin winner key (min d, ties -> lowest k)
// ---------------------------------------------------------------------------
__global__ __launch_bounds__(256) void passB_kernel(const float* __restrict__ emb) {
    const unsigned cnt = min(g_cnt, (unsigned)LIST_CAP);
    const unsigned stride = gridDim.x * 256;
    for (unsigned i = blockIdx.x * 256 + threadIdx.x; i < cnt; i += stride) {
        const unsigned e = g_list[i];
        const int row = e >> 13;
        const int k   = e & 8191;
        const float zn = g_znorm[row];
        const float4* zr = (const float4*)(g_zt + (size_t)row * DDIM);
        const float4* er = (const float4*)(emb + (size_t)k * DDIM);
        float s = 0.f;
        #pragma unroll
        for (int d4 = 0; d4 < 16; ++d4) {
            float4 av = zr[d4];
            float4 bv = er[d4];
            s = __fmaf_rn(av.x, bv.x, s);
            s = __fmaf_rn(av.y, bv.y, s);
            s = __fmaf_rn(av.z, bv.z, s);
            s = __fmaf_rn(av.w, bv.w, s);
        }
        float d = __fsub_rn(__fadd_rn(zn, g_enorm[k]), __fmul_rn(2.f, s));
        ull key = ((ull)__float_as_uint(d) << 32) | (unsigned)k;
        atomicMin(&g_win[row], key);
    }
}

// ---------------------------------------------------------------------------
// gather: z_q = fl(z + fl(zq - z)) (exact reference ops), loss partials, idx
// ---------------------------------------------------------------------------
__global__ __launch_bounds__(256) void gather_kernel(
    const float* __restrict__ z, const float* __restrict__ emb,
    float* __restrict__ out, int out_size)
{
    const int n = blockIdx.x * 256 + threadIdx.x;
    const int idx = (int)(g_win[n] & 8191u);
    const int obase = (n >> 12) * 262144 + (n & 4095);

    const float4* er = (const float4*)(emb + (size_t)idx * DDIM);
    float acc = 0.f;
    #pragma unroll
    for (int i = 0; i < DDIM / 4; ++i) {
        float4 e4 = er[i];
        float ev[4] = {e4.x, e4.y, e4.z, e4.w};
        #pragma unroll
        for (int c = 0; c < 4; ++c) {
            int d = 4 * i + c;
            float zv = z[obase + d * 4096];
            float df = __fsub_rn(ev[c], zv);
            out[obase + d * 4096] = __fadd_rn(zv, df);
            acc = fmaf(df, df, acc);
        }
    }
    if (out_size >= ZQ_ELEMS + 1 + N_TOT)
        out[ZQ_ELEMS + 1 + n] = (float)idx;

    __shared__ float red[256];
    red[threadIdx.x] = acc;
    __syncthreads();
    #pragma unroll
    for (int s = 128; s > 0; s >>= 1) {
        if (threadIdx.x < s) red[threadIdx.x] += red[threadIdx.x + s];
        __syncthreads();
    }
    if (threadIdx.x == 0) g_partial[blockIdx.x] = red[0];
}

__global__ void loss_kernel(float* __restrict__ out, int out_size) {
    __shared__ float red[128];
    red[threadIdx.x] = g_partial[threadIdx.x];
    __syncthreads();
    #pragma unroll
    for (int s = 64; s > 0; s >>= 1) {
        if (threadIdx.x < s) red[threadIdx.x] += red[threadIdx.x + s];
        __syncthreads();
    }
    if (threadIdx.x == 0 && out_size >= ZQ_ELEMS + 1) {
        float m = red[0] / (float)ZQ_ELEMS;
        out[ZQ_ELEMS] = __fadd_rn(m, __fmul_rn(0.25f, m));
    }
}

// ---------------------------------------------------------------------------
extern "C" void kernel_launch(void* const* d_in, const int* in_sizes, int n_in,
                              void* d_out, int out_size) {
    const float* z   = (const float*)d_in[0];
    const float* emb = (const float*)d_in[1];
    float* out = (float*)d_out;

    const int SMEM_A = 16384 + 33024;   // B bufs + padded z staging / candidates
    static int smem_set = 0;
    if (!smem_set) {
        cudaFuncSetAttribute(passA_kernel,
            cudaFuncAttributeMaxDynamicSharedMemorySize, SMEM_A);
        smem_set = 1;
    }

    prep_kernel<<<K_TOT / 256, 256>>>(emb);
    passA_kernel<<<N_TOT / M_CTA, 256, SMEM_A>>>(z);
    passB_kernel<<<256, 256>>>(emb);
    gather_kernel<<<N_TOT / 256, 256>>>(z, emb, out, out_size);
    loss_kernel<<<1, 128>>>(out, out_size);
}

// round 15
// speedup vs baseline: 1.9842x; 1.0101x over previous
#include <cuda_runtime.h>
#include <cuda_bf16.h>
#include <cstdint>

#define N_TOT 32768
#define K_TOT 8192
#define DDIM  64
#define ZQ_ELEMS 2097152
#define M_CTA 128
#define NB    64                  // codes per tile
#define NTILES (K_TOT / NB)       // 128
#define EPS_DOT 6e-5f
#define LIST_CAP (1u << 20)
#define CAND_CAP 2048
#define ZS_STRIDE 129             // padded staging stride (conflict-free)

typedef unsigned long long ull;

// device scratch (no cudaMalloc allowed)
__device__ float g_enorm[K_TOT];
__device__ float g_znorm[N_TOT];
__device__ __align__(16) float g_zt[N_TOT * DDIM];             // 8MB z transposed
__device__ __align__(16) __nv_bfloat16 g_ebf16[K_TOT * DDIM];  // 1MB
__device__ unsigned g_list[LIST_CAP];                          // survivors (row<<13|k)
__device__ unsigned g_cnt;
__device__ ull   g_win[N_TOT];
__device__ float g_partial[128];

// ---------------- helpers ----------------
__device__ __forceinline__ uint32_t smem_u32(const void* p) {
    uint32_t a;
    asm("{ .reg .u64 t; cvta.to.shared.u64 t, %1; cvt.u32.u64 %0, t; }"
        : "=r"(a) : "l"(p));
    return a;
}
__device__ __forceinline__ unsigned packbf(float lo, float hi) {
    __nv_bfloat162 t = __floats2bfloat162_rn(lo, hi);
    return *reinterpret_cast<unsigned*>(&t);
}
__device__ __forceinline__ void mma16816(float c[4], const unsigned a[4],
                                         unsigned b0, unsigned b1) {
    asm volatile(
        "mma.sync.aligned.m16n8k16.row.col.f32.bf16.bf16.f32 "
        "{%0,%1,%2,%3}, {%4,%5,%6,%7}, {%8,%9}, {%0,%1,%2,%3};\n"
        : "+f"(c[0]), "+f"(c[1]), "+f"(c[2]), "+f"(c[3])
        : "r"(a[0]), "r"(a[1]), "r"(a[2]), "r"(a[3]), "r"(b0), "r"(b1));
}
__device__ __forceinline__ void cp16(uint32_t saddr, const void* gaddr) {
    asm volatile("cp.async.ca.shared.global [%0], [%1], 16;\n"
                 :: "r"(saddr), "l"(gaddr));
}

// ---------------------------------------------------------------------------
// prep: ||e||^2 exact (reference order) + bf16 copy + g_win/g_cnt init
// ---------------------------------------------------------------------------
__global__ void prep_kernel(const float* __restrict__ emb) {
    if (blockIdx.x == 0 && threadIdx.x == 0) g_cnt = 0;
    int k = blockIdx.x * blockDim.x + threadIdx.x;
    if (k < K_TOT) {
        const float* r = emb + (size_t)k * DDIM;
        __nv_bfloat16* o = g_ebf16 + (size_t)k * DDIM;
        float s = 0.f;
        #pragma unroll
        for (int c = 0; c < DDIM; ++c) {
            float v = r[c];
            s = __fadd_rn(s, __fmul_rn(v, v));
            o[c] = __float2bfloat16(v);
        }
        g_enorm[k] = s;
        #pragma unroll
        for (int j = 0; j < 4; ++j) g_win[k + j * K_TOT] = ~0ull;
    }
}

// ---------------------------------------------------------------------------
// Pass A (fused): z staging + znorm + g_zt + bf16 mma GEMM + rowmax +
// candidate emission + final refilter.
// grid = 256 CTAs (128 rows) x 256 threads (8 warps x 16 rows).
// __launch_bounds__(256, 3): cap regs at 84 -> 3 CTAs/SM = 6 warps/SMSP.
// dyn smem 49408B: [0,16K) B double buffer
//                  [16K, +33024) phase 1: padded z staging [64][129]
//                  (mainloop overlay) [16K,24K) cand_tag | [24K,32K) cand_val
// ---------------------------------------------------------------------------
__global__ __launch_bounds__(256, 3) void passA_kernel(const float* __restrict__ z) {
    extern __shared__ __align__(16) char smem[];
    float*    zs       = (float*)(smem + 16384);        // [64][129] floats
    unsigned* cand_tag = (unsigned*)(smem + 16384);     // 2048 (overlay)
    float*    cand_val = (float*)(smem + 24576);        // 2048 (overlay)
    __shared__ unsigned s_cnt;
    __shared__ float rowmaxs[M_CTA];

    const int tid  = threadIdx.x;
    const int lane = tid & 31;
    const int w    = tid >> 5;
    const int n0   = blockIdx.x * M_CTA;
    const int zbase = (n0 >> 12) * 262144 + (n0 & 4095);
    const uint32_t bbase = smem_u32(smem);

    if (tid == 0) s_cnt = 0;

    // stage B tile 0 into buffer 0 via cp.async (16B XOR swizzle in code rows)
    {
        const char* src = (const char*)g_ebf16;
        #pragma unroll
        for (int i = 0; i < 2; ++i) {
            int q = tid + 256 * i;
            int code = q >> 3, j = q & 7;
            cp16(bbase + (code * 8 + (j ^ (code & 7))) * 16, src + q * 16);
        }
        asm volatile("cp.async.commit_group;\n");
    }

    // ---- phase 1: stage z [d][r] padded (coalesced gmem, clean smem) ----
    #pragma unroll
    for (int i = 0; i < 32; ++i) {
        int f = tid + 256 * i;
        int d = f >> 7, r = f & 127;
        zs[d * ZS_STRIDE + r] = z[zbase + d * 4096 + r];
    }
    __syncthreads();

    // znorm (bit-exact sequential c=0..63) for this CTA's 128 rows
    if (tid < 128) {
        float s = 0.f;
        #pragma unroll
        for (int c = 0; c < DDIM; ++c) {
            float v = zs[c * ZS_STRIDE + tid];
            s = __fadd_rn(s, __fmul_rn(v, v));
        }
        g_znorm[n0 + tid] = s;
    }
    // write g_zt rows (conflict-free smem reads, coalesced gmem writes)
    #pragma unroll
    for (int i = 0; i < 32; ++i) {
        int f = tid + 256 * i;
        int r = f >> 6, d = f & 63;
        g_zt[(size_t)(n0 + r) * DDIM + d] = zs[d * ZS_STRIDE + r];
    }

    const int g  = lane >> 2;
    const int c2 = (lane & 3) * 2;
    const int rl = 16 * w + g;

    // A fragments from padded staging
    unsigned a[4][4];
    #pragma unroll
    for (int s = 0; s < 4; ++s) {
        int k0 = 16 * s + c2;
        a[s][0] = packbf(zs[k0 * ZS_STRIDE + rl],           zs[(k0 + 1) * ZS_STRIDE + rl]);
        a[s][1] = packbf(zs[k0 * ZS_STRIDE + rl + 8],       zs[(k0 + 1) * ZS_STRIDE + rl + 8]);
        a[s][2] = packbf(zs[(k0 + 8) * ZS_STRIDE + rl],     zs[(k0 + 9) * ZS_STRIDE + rl]);
        a[s][3] = packbf(zs[(k0 + 8) * ZS_STRIDE + rl + 8], zs[(k0 + 9) * ZS_STRIDE + rl + 8]);
    }
    asm volatile("cp.async.wait_group 0;\n" ::: "memory");
    __syncthreads();   // zs region becomes candidate arrays

    const int bn = lane & 7;          // code row within nt block
    const int jg = lane >> 3;         // 16B-chunk group for ldmatrix.x4
    const unsigned row0 = n0 + rl;    // rows for cf[.][0..1]; +8 for [2..3]

    float m0run = -1e30f, m1run = -1e30f;

    for (int t = 0; t < NTILES; ++t) {
        const uint32_t cur = bbase + (t & 1) * 8192;

        if (t + 1 < NTILES) {
            const char* src = (const char*)(g_ebf16 + (size_t)(t + 1) * NB * DDIM);
            const uint32_t dst = bbase + ((t + 1) & 1) * 8192;
            #pragma unroll
            for (int i = 0; i < 2; ++i) {
                int q = tid + 256 * i;
                int code = q >> 3, j = q & 7;
                cp16(dst + (code * 8 + (j ^ (code & 7))) * 16, src + q * 16);
            }
        }
        asm volatile("cp.async.commit_group;\n");

        float cf[8][4];
        #pragma unroll
        for (int nt = 0; nt < 8; ++nt) {
            cf[nt][0] = cf[nt][1] = cf[nt][2] = cf[nt][3] = 0.f;
            int code = nt * 8 + bn;
            uint32_t rowb = cur + code * 128;
            unsigned r0, r1, r2, r3, r4, r5, r6, r7;
            uint32_t ad0 = rowb + (jg ^ (code & 7)) * 16;
            asm volatile("ldmatrix.sync.aligned.m8n8.x4.shared.b16 {%0,%1,%2,%3}, [%4];"
                         : "=r"(r0), "=r"(r1), "=r"(r2), "=r"(r3) : "r"(ad0));
            uint32_t ad1 = rowb + ((jg + 4) ^ (code & 7)) * 16;
            asm volatile("ldmatrix.sync.aligned.m8n8.x4.shared.b16 {%0,%1,%2,%3}, [%4];"
                         : "=r"(r4), "=r"(r5), "=r"(r6), "=r"(r7) : "r"(ad1));
            mma16816(cf[nt], a[0], r0, r1);
            mma16816(cf[nt], a[1], r2, r3);
            mma16816(cf[nt], a[2], r4, r5);
            mma16816(cf[nt], a[3], r6, r7);
        }

        // per-thread local maxima, then 4-lane-group row max
        float l0 = fmaxf(cf[0][0], cf[0][1]), l1 = fmaxf(cf[0][2], cf[0][3]);
        #pragma unroll
        for (int nt = 1; nt < 8; ++nt) {
            l0 = fmaxf(l0, fmaxf(cf[nt][0], cf[nt][1]));
            l1 = fmaxf(l1, fmaxf(cf[nt][2], cf[nt][3]));
        }
        float m0 = fmaxf(l0, __shfl_xor_sync(~0u, l0, 1));
        m0 = fmaxf(m0, __shfl_xor_sync(~0u, m0, 2));
        float m1 = fmaxf(l1, __shfl_xor_sync(~0u, l1, 1));
        m1 = fmaxf(m1, __shfl_xor_sync(~0u, m1, 2));
        m0run = fmaxf(m0run, m0);
        m1run = fmaxf(m1run, m1);

        // rare: emit candidates vs running rowmax (superset of final survivors)
        const float th0 = m0run - EPS_DOT;
        const float th1 = m1run - EPS_DOT;
        if (l0 >= th0) {
            #pragma unroll
            for (int nt = 0; nt < 8; ++nt)
                #pragma unroll
                for (int q = 0; q < 2; ++q)
                    if (cf[nt][q] >= th0) {
                        unsigned tag = (row0 << 13) | (t * 64 + nt * 8 + c2 + q);
                        unsigned p = atomicAdd(&s_cnt, 1u);
                        if (p < CAND_CAP) { cand_tag[p] = tag; cand_val[p] = cf[nt][q]; }
                        else { unsigned gp = atomicAdd(&g_cnt, 1u);
                               if (gp < LIST_CAP) g_list[gp] = tag; }
                    }
        }
        if (l1 >= th1) {
            #pragma unroll
            for (int nt = 0; nt < 8; ++nt)
                #pragma unroll
                for (int q = 0; q < 2; ++q)
                    if (cf[nt][2 + q] >= th1) {
                        unsigned tag = ((row0 + 8) << 13) | (t * 64 + nt * 8 + c2 + q);
                        unsigned p = atomicAdd(&s_cnt, 1u);
                        if (p < CAND_CAP) { cand_tag[p] = tag; cand_val[p] = cf[nt][2 + q]; }
                        else { unsigned gp = atomicAdd(&g_cnt, 1u);
                               if (gp < LIST_CAP) g_list[gp] = tag; }
                    }
        }

        asm volatile("cp.async.wait_group 0;\n" ::: "memory");
        __syncthreads();
    }

    // final per-row maxima, refilter candidates, flush survivors
    if ((lane & 3) == 0) {
        rowmaxs[rl] = m0run;
        rowmaxs[rl + 8] = m1run;
    }
    __syncthreads();

    {
        const unsigned nloc = min(s_cnt, (unsigned)CAND_CAP);
        for (unsigned i = tid; i < nloc; i += 256) {
            unsigned tag = cand_tag[i];
            int rloc = (int)(tag >> 13) - n0;
            if (cand_val[i] >= rowmaxs[rloc] - EPS_DOT) {
                unsigned p = atomicAdd(&g_cnt, 1u);
                if (p < LIST_CAP) g_list[p] = tag;
            }
        }
    }
}

// ---------------------------------------------------------------------------
// Pass B: one thread per survivor (row,k); bit-exact sequential fp32 chain;
// atomicMin winner key (min d, ties -> lowest k)
// ---------------------------------------------------------------------------
__global__ __launch_bounds__(256) void passB_kernel(const float* __restrict__ emb) {
    const unsigned cnt = min(g_cnt, (unsigned)LIST_CAP);
    const unsigned stride = gridDim.x * 256;
    for (unsigned i = blockIdx.x * 256 + threadIdx.x; i < cnt; i += stride) {
        const unsigned e = g_list[i];
        const int row = e >> 13;
        const int k   = e & 8191;
        const float zn = g_znorm[row];
        const float4* zr = (const float4*)(g_zt + (size_t)row * DDIM);
        const float4* er = (const float4*)(emb + (size_t)k * DDIM);
        float s = 0.f;
        #pragma unroll
        for (int d4 = 0; d4 < 16; ++d4) {
            float4 av = zr[d4];
            float4 bv = er[d4];
            s = __fmaf_rn(av.x, bv.x, s);
            s = __fmaf_rn(av.y, bv.y, s);
            s = __fmaf_rn(av.z, bv.z, s);
            s = __fmaf_rn(av.w, bv.w, s);
        }
        float d = __fsub_rn(__fadd_rn(zn, g_enorm[k]), __fmul_rn(2.f, s));
        ull key = ((ull)__float_as_uint(d) << 32) | (unsigned)k;
        atomicMin(&g_win[row], key);
    }
}

// ---------------------------------------------------------------------------
// gather: z_q = fl(z + fl(zq - z)) (exact reference ops), loss partials, idx
// ---------------------------------------------------------------------------
__global__ __launch_bounds__(256) void gather_kernel(
    const float* __restrict__ z, const float* __restrict__ emb,
    float* __restrict__ out, int out_size)
{
    const int n = blockIdx.x * 256 + threadIdx.x;
    const int idx = (int)(g_win[n] & 8191u);
    const int obase = (n >> 12) * 262144 + (n & 4095);

    const float4* er = (const float4*)(emb + (size_t)idx * DDIM);
    float acc = 0.f;
    #pragma unroll
    for (int i = 0; i < DDIM / 4; ++i) {
        float4 e4 = er[i];
        float ev[4] = {e4.x, e4.y, e4.z, e4.w};
        #pragma unroll
        for (int c = 0; c < 4; ++c) {
            int d = 4 * i + c;
            float zv = z[obase + d * 4096];
            float df = __fsub_rn(ev[c], zv);
            out[obase + d * 4096] = __fadd_rn(zv, df);
            acc = fmaf(df, df, acc);
        }
    }
    if (out_size >= ZQ_ELEMS + 1 + N_TOT)
        out[ZQ_ELEMS + 1 + n] = (float)idx;

    __shared__ float red[256];
    red[threadIdx.x] = acc;
    __syncthreads();
    #pragma unroll
    for (int s = 128; s > 0; s >>= 1) {
        if (threadIdx.x < s) red[threadIdx.x] += red[threadIdx.x + s];
        __syncthreads();
    }
    if (threadIdx.x == 0) g_partial[blockIdx.x] = red[0];
}

__global__ void loss_kernel(float* __restrict__ out, int out_size) {
    __shared__ float red[128];
    red[threadIdx.x] = g_partial[threadIdx.x];
    __syncthreads();
    #pragma unroll
    for (int s = 64; s > 0; s >>= 1) {
        if (threadIdx.x < s) red[threadIdx.x] += red[threadIdx.x + s];
        __syncthreads();
    }
    if (threadIdx.x == 0 && out_size >= ZQ_ELEMS + 1) {
        float m = red[0] / (float)ZQ_ELEMS;
        out[ZQ_ELEMS] = __fadd_rn(m, __fmul_rn(0.25f, m));
    }
}

// ---------------------------------------------------------------------------
extern "C" void kernel_launch(void* const* d_in, const int* in_sizes, int n_in,
                              void* d_out, int out_size) {
    const float* z   = (const float*)d_in[0];
    const float* emb = (const float*)d_in[1];
    float* out = (float*)d_out;

    const int SMEM_A = 16384 + 33024;   // B bufs + padded z staging / candidates
    static int smem_set = 0;
    if (!smem_set) {
        cudaFuncSetAttribute(passA_kernel,
            cudaFuncAttributeMaxDynamicSharedMemorySize, SMEM_A);
        smem_set = 1;
    }

    prep_kernel<<<K_TOT / 256, 256>>>(emb);
    passA_kernel<<<N_TOT / M_CTA, 256, SMEM_A>>>(z);
    passB_kernel<<<256, 256>>>(emb);
    gather_kernel<<<N_TOT / 256, 256>>>(z, emb, out, out_size);
    loss_kernel<<<1, 128>>>(out, out_size);
}